// round 14
// baseline (speedup 1.0000x reference)
#include <cuda_runtime.h>
#include <cuda_fp16.h>
#include <cstdint>

// Problem shape (fixed)
#define Bb   2
#define Hh   16
#define Mm   2048
#define Nn   2048
#define Ccon 1024
#define HD   64

#define QSCALE 0.18033688f   // 0.125 * log2(e); P = 2^(Q'.K)

// ---------------------------------------------------------------------------
// Device-global scratch (single fp16)
// ---------------------------------------------------------------------------
__device__ __align__(128) __half g_tgt[4194304];    // [b*M][C]
__device__ __align__(128) __half g_ref[4194304];    // [b*N][C]
__device__ __align__(128) __half g_Wq [1048576];    // [N][K] (transposed)
__device__ __align__(128) __half g_Wkv[2097152];    // [N][K]
__device__ __align__(128) __half g_Wp [1048576];    // [N][K]
__device__ __align__(128) __half g_Q [4194304];     // [bh][m][d] (x QSCALE)
__device__ __align__(128) __half g_K [4194304];     // [bh][n][d]
__device__ __align__(128) __half g_Vt[4194304];     // [bh][d][n]
__device__ __align__(128) __half g_X [4194304];     // [b*M][C]

// ---------------------------------------------------------------------------
// Helpers (plain sm_80+ PTX)
// ---------------------------------------------------------------------------
__device__ __forceinline__ uint32_t smem_u32(const void* p) {
    uint32_t a;
    asm("{ .reg .u64 t; cvta.to.shared.u64 t, %1; cvt.u32.u64 %0, t; }" : "=r"(a) : "l"(p));
    return a;
}
__device__ __forceinline__ void cp16(uint32_t s, const void* g) {
    asm volatile("cp.async.cg.shared.global [%0], [%1], 16;" :: "r"(s), "l"(g));
}
#define CP_COMMIT() asm volatile("cp.async.commit_group;" ::: "memory")
#define CP_WAIT(n)  asm volatile("cp.async.wait_group %0;" :: "n"(n) : "memory")

__device__ __forceinline__ void ldsm4(uint32_t r[4], uint32_t a) {
    asm volatile("ldmatrix.sync.aligned.m8n8.x4.shared.b16 {%0,%1,%2,%3}, [%4];"
        : "=r"(r[0]), "=r"(r[1]), "=r"(r[2]), "=r"(r[3]) : "r"(a));
}
__device__ __forceinline__ void mma16816(float c[4], const uint32_t a[4], const uint32_t b[2]) {
    asm volatile("mma.sync.aligned.m16n8k16.row.col.f32.f16.f16.f32 "
        "{%0,%1,%2,%3}, {%4,%5,%6,%7}, {%8,%9}, {%0,%1,%2,%3};"
        : "+f"(c[0]), "+f"(c[1]), "+f"(c[2]), "+f"(c[3])
        : "r"(a[0]), "r"(a[1]), "r"(a[2]), "r"(a[3]), "r"(b[0]), "r"(b[1]));
}
__device__ __forceinline__ uint32_t pack2h(float a, float b) {
    __half2 v = __floats2half2_rn(a, b);
    return *(uint32_t*)&v;
}
__device__ __forceinline__ uint32_t h2ex2(uint32_t x) {
    uint32_t r;
    asm("ex2.approx.f16x2 %0, %1;" : "=r"(r) : "r"(x));
    return r;
}
__device__ __forceinline__ float2 h22f2(uint32_t x) {
    __half2 h = *(__half2*)&x;
    return __half22float2(h);
}
__device__ __forceinline__ uint32_t hadd2u(uint32_t a, uint32_t b) {
    __half2 r = __hadd2(*(__half2*)&a, *(__half2*)&b);
    return *(uint32_t*)&r;
}

// ---------------------------------------------------------------------------
// Prep: activations fp32->fp16 (one launch), weights transpose+convert
// ---------------------------------------------------------------------------
__global__ __launch_bounds__(256) void convert_acts(const float* __restrict__ tgt,
                                                    const float* __restrict__ ref) {
    int i = blockIdx.x * 256 + threadIdx.x;          // 0..2M-1 float4s
    const bool second = i >= 1048576;
    const float* in = second ? ref : tgt;
    __half* o = second ? g_ref : g_tgt;
    int j = second ? i - 1048576 : i;
    float4 v = ((const float4*)in)[j];
    uint2 hv = { pack2h(v.x, v.y), pack2h(v.z, v.w) };
    *(uint2*)(o + (size_t)j * 4) = hv;
}

__global__ __launch_bounds__(256) void transpose_ws(const float* __restrict__ Wq,
                                                    const float* __restrict__ Wkv,
                                                    const float* __restrict__ Wp) {
    const int z = blockIdx.z;
    if (z != 1 && blockIdx.x >= 32) return;
    const float* W = z == 0 ? Wq : (z == 1 ? Wkv : Wp);
    __half* o = z == 0 ? g_Wq : (z == 1 ? g_Wkv : g_Wp);
    const int Ntot = z == 1 ? 2048 : 1024;
    __shared__ float t[32][33];
    int n0 = blockIdx.x * 32, k0 = blockIdx.y * 32;
    int x = threadIdx.x & 31, y = threadIdx.x >> 5;
#pragma unroll
    for (int i = 0; i < 32; i += 8)
        t[y + i][x] = W[(size_t)(k0 + y + i) * Ntot + n0 + x];
    __syncthreads();
#pragma unroll
    for (int i = 0; i < 32; i += 8)
        o[(size_t)(n0 + y + i) * 1024 + k0 + x] = __float2half_rn(t[x][y + i]);
}

// ---------------------------------------------------------------------------
// GEMM core (R10/R11 exact): 128x128 tile, 8 warps (2x4, each 64x32),
// K-stage 32, 4-stage cp.async pipeline, 2 CTAs/SM.
// ---------------------------------------------------------------------------
#define RB     80                         // smem row bytes (32 halves + pad)
#define ATILE  (128 * RB)                 // 10240
#define BTILE  (128 * RB)                 // 10240
#define GSTG   (ATILE + BTILE)            // 20480
#define GEMM_SMEM (4 * GSTG)              // 81920

__device__ __forceinline__ void gemm_core(
    float acc[4][4][4],
    const __half* __restrict__ A, const __half* __restrict__ Bw,
    int bm, int bn, uint32_t sb)
{
    const int tid = threadIdx.x, lane = tid & 31, w = tid >> 5;
    const int wm = w >> 2, wn = w & 3;     // 2 x 4 warps, warp tile 64x32

    auto load_stage = [&](int s, int buf) {
        const int k0 = s * 32;
        const uint32_t base = sb + (uint32_t)buf * GSTG;
#pragma unroll
        for (int it = 0; it < 2; it++) {
            int f = tid + it * 256;
            int r = f >> 2, c = f & 3;
            cp16(base + (uint32_t)(r * RB + c * 16),
                 A + (size_t)(bm + r) * 1024 + k0 + c * 8);
        }
#pragma unroll
        for (int it = 0; it < 2; it++) {
            int f = tid + it * 256;
            int r = f >> 2, c = f & 3;
            cp16(base + ATILE + (uint32_t)(r * RB + c * 16),
                 Bw + (size_t)(bn + r) * 1024 + k0 + c * 8);
        }
    };

#pragma unroll
    for (int i = 0; i < 4; i++)
#pragma unroll
        for (int j = 0; j < 4; j++)
#pragma unroll
            for (int k = 0; k < 4; k++) acc[i][j][k] = 0.0f;

    load_stage(0, 0); CP_COMMIT();
    load_stage(1, 1); CP_COMMIT();
    load_stage(2, 2); CP_COMMIT();

    const uint32_t mi = (uint32_t)(lane >> 3);
    const uint32_t prow = ((mi >> 1) << 3) + (lane & 7);
    const uint32_t pcol = (mi & 1) << 4;

#pragma unroll 1
    for (int s = 0; s < 32; s++) {
        CP_WAIT(2);
        __syncthreads();
        if (s + 3 < 32) load_stage(s + 3, (s + 3) & 3);
        CP_COMMIT();
        const uint32_t tb = sb + (uint32_t)(s & 3) * GSTG;
#pragma unroll
        for (int kc = 0; kc < 2; kc++) {
            uint32_t ah[4][4], bq[2][4];
#pragma unroll
            for (int mf = 0; mf < 4; mf++) {
                uint32_t off = (uint32_t)((wm * 64 + mf * 16 + (lane & 15)) * RB
                             + kc * 32 + (lane >> 4) * 16);
                ldsm4(ah[mf], tb + off);
            }
#pragma unroll
            for (int np = 0; np < 2; np++) {
                uint32_t off = (uint32_t)((wn * 32 + np * 16 + prow) * RB
                             + kc * 32 + pcol);
                ldsm4(bq[np], tb + ATILE + off);
            }
#pragma unroll
            for (int mf = 0; mf < 4; mf++)
#pragma unroll
                for (int np = 0; np < 2; np++) {
                    mma16816(acc[mf][2 * np],     ah[mf], bq[np]);
                    mma16816(acc[mf][2 * np + 1], ah[mf], bq[np] + 2);
                }
        }
    }
}

// Merged Q-proj + KV-proj: grid (24, 32). x<8 -> Q (tgt@Wq), else KV (ref@Wkv).
__global__ __launch_bounds__(256, 2) void gemm01() {
    extern __shared__ __align__(16) char sm[];
    const uint32_t sb = smem_u32(sm);
    const int tid = threadIdx.x, lane = tid & 31, w = tid >> 5;
    const int wm = w >> 2, wn = w & 3;
    const bool qm = blockIdx.x < 8;
    const int bm = blockIdx.y * 128;
    const int bn = (qm ? blockIdx.x : blockIdx.x - 8) * 128;

    float acc[4][4][4];
    gemm_core(acc, qm ? g_tgt : g_ref, qm ? g_Wq : g_Wkv, bm, bn, sb);

#pragma unroll
    for (int mf = 0; mf < 4; mf++)
#pragma unroll
        for (int nf = 0; nf < 4; nf++) {
            int r0 = bm + wm * 64 + mf * 16 + (lane >> 2);
            int cc = bn + wn * 32 + nf * 8 + 2 * (lane & 3);
            float* a = acc[mf][nf];
#pragma unroll
            for (int hf = 0; hf < 2; hf++) {
                int r = r0 + hf * 8;
                float v0 = a[hf * 2], v1 = a[hf * 2 + 1];
                int b = r >> 11, row = r & 2047;
                if (qm) {
                    int h = cc >> 6, d = cc & 63;
                    size_t o = ((size_t)((b * 16 + h) * 2048 + row)) * 64 + d;
                    *(uint32_t*)(g_Q + o) = pack2h(v0 * QSCALE, v1 * QSCALE);
                } else if (cc < 1024) {
                    int h = cc >> 6, d = cc & 63;
                    size_t o = ((size_t)((b * 16 + h) * 2048 + row)) * 64 + d;
                    *(uint32_t*)(g_K + o) = pack2h(v0, v1);
                } else {
                    int cc2 = cc - 1024, h = cc2 >> 6, d = cc2 & 63;
                    size_t o = ((size_t)((b * 16 + h) * 64 + d)) * 2048 + row;
                    g_Vt[o]        = __float2half_rn(v0);
                    g_Vt[o + 2048] = __float2half_rn(v1);
                }
            }
        }
}

// Output projection: X@Wp + bias -> out (fp32). grid (8, 32).
__global__ __launch_bounds__(256, 2) void gemm2(const float* __restrict__ bias,
                                                float* __restrict__ out) {
    extern __shared__ __align__(16) char sm[];
    const uint32_t sb = smem_u32(sm);
    const int tid = threadIdx.x, lane = tid & 31, w = tid >> 5;
    const int wm = w >> 2, wn = w & 3;
    const int bm = blockIdx.y * 128, bn = blockIdx.x * 128;

    float acc[4][4][4];
    gemm_core(acc, g_X, g_Wp, bm, bn, sb);

#pragma unroll
    for (int mf = 0; mf < 4; mf++)
#pragma unroll
        for (int nf = 0; nf < 4; nf++) {
            int r0 = bm + wm * 64 + mf * 16 + (lane >> 2);
            int cc = bn + wn * 32 + nf * 8 + 2 * (lane & 3);
            float* a = acc[mf][nf];
#pragma unroll
            for (int hf = 0; hf < 2; hf++) {
                int r = r0 + hf * 8;
                float2 ov = { a[hf * 2] + bias[cc], a[hf * 2 + 1] + bias[cc + 1] };
                *(float2*)(out + (size_t)r * 1024 + cc) = ov;
            }
        }
}

// ---------------------------------------------------------------------------
// Flash attention (R11 + HADD2 lsum micro): 4 warps x 32 q-rows (128 thr),
// frag-sharing, f16x2 exp. N chunks of 128, 2-stage pipeline,
// launch_bounds(128,2) — regs free (R11 optimum).
// ---------------------------------------------------------------------------
#define RBQ   144                           // 64 halves + 16B pad
#define RBV   272                           // 128 halves + 16B pad
#define KT    (128 * RBQ)                   // 18432
#define VT    (64 * RBV)                    // 17408
#define ASTG  (KT + VT)                     // 35840
#define ATTN_SMEM (2 * ASTG)                // 71680

__global__ __launch_bounds__(128, 2) void attn_mma() {
    extern __shared__ __align__(16) char sm[];
    const uint32_t sb = smem_u32(sm);
    const int tid = threadIdx.x, lane = tid & 31, w = tid >> 5;   // 4 warps
    const int bh = blockIdx.y, mblk = blockIdx.x * 128;
    const size_t hoff = (size_t)bh * 2048 * 64;

    auto load_chunk = [&](int ch, int buf) {
        const int j0 = ch * 128;
        const uint32_t base = sb + (uint32_t)buf * ASTG;
#pragma unroll
        for (int it = 0; it < 8; it++) {
            int f = tid + it * 128;              // 0..1023
            int rk = f >> 3, ck = f & 7;         // K: 128 rows x 8 chunks
            cp16(base + (uint32_t)(rk * RBQ + ck * 16),
                 g_K + hoff + (size_t)(j0 + rk) * 64 + ck * 8);
            int rv = f >> 4, cv = f & 15;        // Vt: 64 rows x 16 chunks
            cp16(base + KT + (uint32_t)(rv * RBV + cv * 16),
                 g_Vt + hoff + (size_t)rv * 2048 + j0 + cv * 8);
        }
    };

    // Stage Q through buffer 0 (K area), pull to regs (2 m-frags/warp)
#pragma unroll
    for (int it = 0; it < 8; it++) {
        int f = tid + it * 128;
        int r = f >> 3, c = f & 7;
        cp16(sb + (uint32_t)(r * RBQ + c * 16),
             g_Q + hoff + (size_t)(mblk + r) * 64 + c * 8);
    }
    CP_COMMIT(); CP_WAIT(0);
    __syncthreads();
    uint32_t qf[2][4][4];
#pragma unroll
    for (int mf = 0; mf < 2; mf++)
#pragma unroll
        for (int kc = 0; kc < 4; kc++) {
            uint32_t off = (uint32_t)((w * 32 + mf * 16 + (lane & 15)) * RBQ
                         + kc * 32 + (lane >> 4) * 16);
            ldsm4(qf[mf][kc], sb + off);
        }
    __syncthreads();

    load_chunk(0, 0); CP_COMMIT();
    load_chunk(1, 1); CP_COMMIT();

    float O[2][8][4];
#pragma unroll
    for (int mf = 0; mf < 2; mf++)
#pragma unroll
        for (int g = 0; g < 8; g++)
#pragma unroll
            for (int i = 0; i < 4; i++) O[mf][g][i] = 0.0f;
    float lsum[2][2] = {{0.0f, 0.0f}, {0.0f, 0.0f}};

    const uint32_t mi = (uint32_t)(lane >> 3);
    const uint32_t prow = ((mi >> 1) << 3) + (lane & 7);
    const uint32_t pcol = (mi & 1) << 4;

#pragma unroll 1
    for (int ch = 0; ch < 16; ch++) {
        CP_WAIT(1);
        __syncthreads();
        const uint32_t tb = sb + (uint32_t)(ch & 1) * ASTG;

        // Fused per 16-column group: S -> ex2(f16x2) -> P -> PV.
        // K/V fragments loaded ONCE, used by both m-frags.
#pragma unroll
        for (int pc = 0; pc < 8; pc++) {
            float S[2][2][4];
#pragma unroll
            for (int mf = 0; mf < 2; mf++)
#pragma unroll
                for (int i = 0; i < 4; i++) { S[mf][0][i] = 0.0f; S[mf][1][i] = 0.0f; }
#pragma unroll
            for (int kc = 0; kc < 4; kc++) {
                uint32_t kb[4];
                ldsm4(kb, tb + (uint32_t)((pc * 16 + prow) * RBQ + kc * 32 + pcol));
#pragma unroll
                for (int mf = 0; mf < 2; mf++) {
                    mma16816(S[mf][0], qf[mf][kc], kb);
                    mma16816(S[mf][1], qf[mf][kc], kb + 2);
                }
            }
            uint32_t pa[2][4];
#pragma unroll
            for (int mf = 0; mf < 2; mf++) {
                pa[mf][0] = h2ex2(pack2h(S[mf][0][0], S[mf][0][1]));
                pa[mf][1] = h2ex2(pack2h(S[mf][0][2], S[mf][0][3]));
                pa[mf][2] = h2ex2(pack2h(S[mf][1][0], S[mf][1][1]));
                pa[mf][3] = h2ex2(pack2h(S[mf][1][2], S[mf][1][3]));
                // HADD2 tree: row-r pairs (pa0+pa2), row-(r+8) pairs (pa1+pa3)
                float2 f0 = h22f2(hadd2u(pa[mf][0], pa[mf][2]));
                float2 f1 = h22f2(hadd2u(pa[mf][1], pa[mf][3]));
                lsum[mf][0] += f0.x + f0.y;
                lsum[mf][1] += f1.x + f1.y;
            }
#pragma unroll
            for (int vg = 0; vg < 4; vg++) {
                uint32_t vb[4];
                ldsm4(vb, tb + KT + (uint32_t)((vg * 16 + prow) * RBV + pc * 32 + pcol));
#pragma unroll
                for (int mf = 0; mf < 2; mf++) {
                    mma16816(O[mf][2 * vg],     pa[mf], vb);
                    mma16816(O[mf][2 * vg + 1], pa[mf], vb + 2);
                }
            }
        }
        __syncthreads();
        if (ch + 2 < 16) load_chunk(ch + 2, ch & 1);
        CP_COMMIT();
    }

    // Row sums over each quad, normalize, store X
#pragma unroll
    for (int mf = 0; mf < 2; mf++)
#pragma unroll
        for (int hf = 0; hf < 2; hf++) {
            lsum[mf][hf] += __shfl_xor_sync(0xffffffffu, lsum[mf][hf], 1, 4);
            lsum[mf][hf] += __shfl_xor_sync(0xffffffffu, lsum[mf][hf], 2, 4);
        }

    const int b = bh >> 4, h = bh & 15;
#pragma unroll
    for (int mf = 0; mf < 2; mf++) {
        const float inv0 = 1.0f / lsum[mf][0], inv1 = 1.0f / lsum[mf][1];
        const int m0 = mblk + w * 32 + mf * 16 + (lane >> 2);
#pragma unroll
        for (int gd = 0; gd < 8; gd++) {
            int cc = h * 64 + gd * 8 + 2 * (lane & 3);
            size_t o = (size_t)(b * 2048 + m0) * 1024 + cc;
            *(uint32_t*)(g_X + o) = pack2h(O[mf][gd][0] * inv0, O[mf][gd][1] * inv0);
            o = (size_t)(b * 2048 + m0 + 8) * 1024 + cc;
            *(uint32_t*)(g_X + o) = pack2h(O[mf][gd][2] * inv1, O[mf][gd][3] * inv1);
        }
    }
}

// ---------------------------------------------------------------------------
extern "C" void kernel_launch(void* const* d_in, const int* in_sizes, int n_in,
                              void* d_out, int out_size)
{
    const float* ref   = (const float*)d_in[0];
    const float* tgt   = (const float*)d_in[1];
    const float* Wq    = (const float*)d_in[2];
    const float* Wkv   = (const float*)d_in[3];
    const float* Wproj = (const float*)d_in[4];
    const float* bproj = (const float*)d_in[5];
    float* out = (float*)d_out;

    cudaFuncSetAttribute(gemm01,   cudaFuncAttributeMaxDynamicSharedMemorySize, GEMM_SMEM);
    cudaFuncSetAttribute(gemm2,    cudaFuncAttributeMaxDynamicSharedMemorySize, GEMM_SMEM);
    cudaFuncSetAttribute(attn_mma, cudaFuncAttributeMaxDynamicSharedMemorySize, ATTN_SMEM);

    convert_acts<<<8192, 256>>>(tgt, ref);
    transpose_ws<<<dim3(64, 32, 3), 256>>>(Wq, Wkv, Wproj);

    gemm01<<<dim3(24, 32), 256, GEMM_SMEM>>>();            // Q-proj + KV-proj merged
    attn_mma<<<dim3(16, 32), 128, ATTN_SMEM>>>();          // attention
    gemm2<<<dim3(8, 32), 256, GEMM_SMEM>>>(bproj, out);    // out-proj
}

// round 15
// speedup vs baseline: 1.0515x; 1.0515x over previous
#include <cuda_runtime.h>
#include <cuda_fp16.h>
#include <cstdint>

// Problem shape (fixed)
#define Bb   2
#define Hh   16
#define Mm   2048
#define Nn   2048
#define Ccon 1024
#define HD   64

#define QSCALE 0.18033688f   // 0.125 * log2(e); P = 2^(Q'.K)

// ---------------------------------------------------------------------------
// Device-global scratch (single fp16)
// ---------------------------------------------------------------------------
__device__ __align__(128) __half g_tgt[4194304];    // [b*M][C]
__device__ __align__(128) __half g_ref[4194304];    // [b*N][C]
__device__ __align__(128) __half g_Wq [1048576];    // [N][K] (transposed)
__device__ __align__(128) __half g_Wkv[2097152];    // [N][K]
__device__ __align__(128) __half g_Wp [1048576];    // [N][K]
__device__ __align__(128) __half g_Q [4194304];     // [bh][m][d] (x QSCALE)
__device__ __align__(128) __half g_K [4194304];     // [bh][n][d]
__device__ __align__(128) __half g_Vt[4194304];     // [bh][d][n]
__device__ __align__(128) __half g_X [4194304];     // [b*M][C]

// ---------------------------------------------------------------------------
// Helpers (plain sm_80+ PTX)
// ---------------------------------------------------------------------------
__device__ __forceinline__ uint32_t smem_u32(const void* p) {
    uint32_t a;
    asm("{ .reg .u64 t; cvta.to.shared.u64 t, %1; cvt.u32.u64 %0, t; }" : "=r"(a) : "l"(p));
    return a;
}
__device__ __forceinline__ void cp16(uint32_t s, const void* g) {
    asm volatile("cp.async.cg.shared.global [%0], [%1], 16;" :: "r"(s), "l"(g));
}
#define CP_COMMIT() asm volatile("cp.async.commit_group;" ::: "memory")
#define CP_WAIT(n)  asm volatile("cp.async.wait_group %0;" :: "n"(n) : "memory")

__device__ __forceinline__ void ldsm4(uint32_t r[4], uint32_t a) {
    asm volatile("ldmatrix.sync.aligned.m8n8.x4.shared.b16 {%0,%1,%2,%3}, [%4];"
        : "=r"(r[0]), "=r"(r[1]), "=r"(r[2]), "=r"(r[3]) : "r"(a));
}
__device__ __forceinline__ void mma16816(float c[4], const uint32_t a[4], const uint32_t b[2]) {
    asm volatile("mma.sync.aligned.m16n8k16.row.col.f32.f16.f16.f32 "
        "{%0,%1,%2,%3}, {%4,%5,%6,%7}, {%8,%9}, {%0,%1,%2,%3};"
        : "+f"(c[0]), "+f"(c[1]), "+f"(c[2]), "+f"(c[3])
        : "r"(a[0]), "r"(a[1]), "r"(a[2]), "r"(a[3]), "r"(b[0]), "r"(b[1]));
}
__device__ __forceinline__ uint32_t pack2h(float a, float b) {
    __half2 v = __floats2half2_rn(a, b);
    return *(uint32_t*)&v;
}
__device__ __forceinline__ uint32_t h2ex2(uint32_t x) {
    uint32_t r;
    asm("ex2.approx.f16x2 %0, %1;" : "=r"(r) : "r"(x));
    return r;
}
__device__ __forceinline__ float2 h22f2(uint32_t x) {
    __half2 h = *(__half2*)&x;
    return __half22float2(h);
}

// ---------------------------------------------------------------------------
// Prep: ONE flat-packed launch, zero wasted blocks.
//   blocks [0, 8192)        : activation fp32->fp16 (2M float4s)
//   blocks [8192, 9216)     : Wq  transpose tiles (32x32 of 1024 n-tiles*k-tiles)
//   blocks [9216, 11264)    : Wkv transpose tiles (2048)
//   blocks [11264, 12288)   : Wp  transpose tiles (1024)
// ---------------------------------------------------------------------------
__global__ __launch_bounds__(256) void prep_all(
    const float* __restrict__ tgt, const float* __restrict__ ref,
    const float* __restrict__ Wq, const float* __restrict__ Wkv,
    const float* __restrict__ Wp)
{
    const int blk = blockIdx.x;
    if (blk < 8192) {
        int i = blk * 256 + threadIdx.x;
        const bool second = i >= 1048576;
        const float* in = second ? ref : tgt;
        __half* o = second ? g_ref : g_tgt;
        int j = second ? i - 1048576 : i;
        float4 v = ((const float4*)in)[j];
        uint2 hv = { pack2h(v.x, v.y), pack2h(v.z, v.w) };
        *(uint2*)(o + (size_t)j * 4) = hv;
        return;
    }
    // Weight transpose tile
    int t = blk - 8192;
    const float* W;
    __half* o;
    int Ntot, tt;
    if (t < 1024)      { W = Wq;  o = g_Wq;  Ntot = 1024; tt = t; }
    else if (t < 3072) { W = Wkv; o = g_Wkv; Ntot = 2048; tt = t - 1024; }
    else               { W = Wp;  o = g_Wp;  Ntot = 1024; tt = t - 3072; }
    const int ntiles = Ntot >> 5;
    const int n0 = (tt % ntiles) * 32, k0 = (tt / ntiles) * 32;

    __shared__ float tb[32][33];
    int x = threadIdx.x & 31, y = threadIdx.x >> 5;
#pragma unroll
    for (int i = 0; i < 32; i += 8)
        tb[y + i][x] = W[(size_t)(k0 + y + i) * Ntot + n0 + x];
    __syncthreads();
#pragma unroll
    for (int i = 0; i < 32; i += 8)
        o[(size_t)(n0 + y + i) * 1024 + k0 + x] = __float2half_rn(tb[x][y + i]);
}

// ---------------------------------------------------------------------------
// GEMM core (R10/R11 exact): 128x128 tile, 8 warps (2x4, each 64x32),
// K-stage 32, 4-stage cp.async pipeline, 2 CTAs/SM.
// ---------------------------------------------------------------------------
#define RB     80                         // smem row bytes (32 halves + pad)
#define ATILE  (128 * RB)                 // 10240
#define BTILE  (128 * RB)                 // 10240
#define GSTG   (ATILE + BTILE)            // 20480
#define GEMM_SMEM (4 * GSTG)              // 81920

__device__ __forceinline__ void gemm_core(
    float acc[4][4][4],
    const __half* __restrict__ A, const __half* __restrict__ Bw,
    int bm, int bn, uint32_t sb)
{
    const int tid = threadIdx.x, lane = tid & 31, w = tid >> 5;
    const int wm = w >> 2, wn = w & 3;     // 2 x 4 warps, warp tile 64x32

    auto load_stage = [&](int s, int buf) {
        const int k0 = s * 32;
        const uint32_t base = sb + (uint32_t)buf * GSTG;
#pragma unroll
        for (int it = 0; it < 2; it++) {
            int f = tid + it * 256;
            int r = f >> 2, c = f & 3;
            cp16(base + (uint32_t)(r * RB + c * 16),
                 A + (size_t)(bm + r) * 1024 + k0 + c * 8);
        }
#pragma unroll
        for (int it = 0; it < 2; it++) {
            int f = tid + it * 256;
            int r = f >> 2, c = f & 3;
            cp16(base + ATILE + (uint32_t)(r * RB + c * 16),
                 Bw + (size_t)(bn + r) * 1024 + k0 + c * 8);
        }
    };

#pragma unroll
    for (int i = 0; i < 4; i++)
#pragma unroll
        for (int j = 0; j < 4; j++)
#pragma unroll
            for (int k = 0; k < 4; k++) acc[i][j][k] = 0.0f;

    load_stage(0, 0); CP_COMMIT();
    load_stage(1, 1); CP_COMMIT();
    load_stage(2, 2); CP_COMMIT();

    const uint32_t mi = (uint32_t)(lane >> 3);
    const uint32_t prow = ((mi >> 1) << 3) + (lane & 7);
    const uint32_t pcol = (mi & 1) << 4;

#pragma unroll 1
    for (int s = 0; s < 32; s++) {
        CP_WAIT(2);
        __syncthreads();
        if (s + 3 < 32) load_stage(s + 3, (s + 3) & 3);
        CP_COMMIT();
        const uint32_t tb = sb + (uint32_t)(s & 3) * GSTG;
#pragma unroll
        for (int kc = 0; kc < 2; kc++) {
            uint32_t ah[4][4], bq[2][4];
#pragma unroll
            for (int mf = 0; mf < 4; mf++) {
                uint32_t off = (uint32_t)((wm * 64 + mf * 16 + (lane & 15)) * RB
                             + kc * 32 + (lane >> 4) * 16);
                ldsm4(ah[mf], tb + off);
            }
#pragma unroll
            for (int np = 0; np < 2; np++) {
                uint32_t off = (uint32_t)((wn * 32 + np * 16 + prow) * RB
                             + kc * 32 + pcol);
                ldsm4(bq[np], tb + ATILE + off);
            }
#pragma unroll
            for (int mf = 0; mf < 4; mf++)
#pragma unroll
                for (int np = 0; np < 2; np++) {
                    mma16816(acc[mf][2 * np],     ah[mf], bq[np]);
                    mma16816(acc[mf][2 * np + 1], ah[mf], bq[np] + 2);
                }
        }
    }
}

// Merged Q-proj + KV-proj: grid (24, 32). x<8 -> Q (tgt@Wq), else KV (ref@Wkv).
__global__ __launch_bounds__(256, 2) void gemm01() {
    extern __shared__ __align__(16) char sm[];
    const uint32_t sb = smem_u32(sm);
    const int tid = threadIdx.x, lane = tid & 31, w = tid >> 5;
    const int wm = w >> 2, wn = w & 3;
    const bool qm = blockIdx.x < 8;
    const int bm = blockIdx.y * 128;
    const int bn = (qm ? blockIdx.x : blockIdx.x - 8) * 128;

    float acc[4][4][4];
    gemm_core(acc, qm ? g_tgt : g_ref, qm ? g_Wq : g_Wkv, bm, bn, sb);

#pragma unroll
    for (int mf = 0; mf < 4; mf++)
#pragma unroll
        for (int nf = 0; nf < 4; nf++) {
            int r0 = bm + wm * 64 + mf * 16 + (lane >> 2);
            int cc = bn + wn * 32 + nf * 8 + 2 * (lane & 3);
            float* a = acc[mf][nf];
#pragma unroll
            for (int hf = 0; hf < 2; hf++) {
                int r = r0 + hf * 8;
                float v0 = a[hf * 2], v1 = a[hf * 2 + 1];
                int b = r >> 11, row = r & 2047;
                if (qm) {
                    int h = cc >> 6, d = cc & 63;
                    size_t o = ((size_t)((b * 16 + h) * 2048 + row)) * 64 + d;
                    *(uint32_t*)(g_Q + o) = pack2h(v0 * QSCALE, v1 * QSCALE);
                } else if (cc < 1024) {
                    int h = cc >> 6, d = cc & 63;
                    size_t o = ((size_t)((b * 16 + h) * 2048 + row)) * 64 + d;
                    *(uint32_t*)(g_K + o) = pack2h(v0, v1);
                } else {
                    int cc2 = cc - 1024, h = cc2 >> 6, d = cc2 & 63;
                    size_t o = ((size_t)((b * 16 + h) * 64 + d)) * 2048 + row;
                    g_Vt[o]        = __float2half_rn(v0);
                    g_Vt[o + 2048] = __float2half_rn(v1);
                }
            }
        }
}

// Output projection: X@Wp + bias -> out (fp32). grid (8, 32).
__global__ __launch_bounds__(256, 2) void gemm2(const float* __restrict__ bias,
                                                float* __restrict__ out) {
    extern __shared__ __align__(16) char sm[];
    const uint32_t sb = smem_u32(sm);
    const int tid = threadIdx.x, lane = tid & 31, w = tid >> 5;
    const int wm = w >> 2, wn = w & 3;
    const int bm = blockIdx.y * 128, bn = blockIdx.x * 128;

    float acc[4][4][4];
    gemm_core(acc, g_X, g_Wp, bm, bn, sb);

#pragma unroll
    for (int mf = 0; mf < 4; mf++)
#pragma unroll
        for (int nf = 0; nf < 4; nf++) {
            int r0 = bm + wm * 64 + mf * 16 + (lane >> 2);
            int cc = bn + wn * 32 + nf * 8 + 2 * (lane & 3);
            float* a = acc[mf][nf];
#pragma unroll
            for (int hf = 0; hf < 2; hf++) {
                int r = r0 + hf * 8;
                float2 ov = { a[hf * 2] + bias[cc], a[hf * 2 + 1] + bias[cc + 1] };
                *(float2*)(out + (size_t)r * 1024 + cc) = ov;
            }
        }
}

// ---------------------------------------------------------------------------
// Flash attention (R11 exact): 4 warps x 32 q-rows (128 thr), frag-sharing,
// f16x2 exp. N chunks of 128, 2-stage pipeline, launch_bounds(128,2).
// ---------------------------------------------------------------------------
#define RBQ   144                           // 64 halves + 16B pad
#define RBV   272                           // 128 halves + 16B pad
#define KT    (128 * RBQ)                   // 18432
#define VT    (64 * RBV)                    // 17408
#define ASTG  (KT + VT)                     // 35840
#define ATTN_SMEM (2 * ASTG)                // 71680

__global__ __launch_bounds__(128, 2) void attn_mma() {
    extern __shared__ __align__(16) char sm[];
    const uint32_t sb = smem_u32(sm);
    const int tid = threadIdx.x, lane = tid & 31, w = tid >> 5;   // 4 warps
    const int bh = blockIdx.y, mblk = blockIdx.x * 128;
    const size_t hoff = (size_t)bh * 2048 * 64;

    auto load_chunk = [&](int ch, int buf) {
        const int j0 = ch * 128;
        const uint32_t base = sb + (uint32_t)buf * ASTG;
#pragma unroll
        for (int it = 0; it < 8; it++) {
            int f = tid + it * 128;              // 0..1023
            int rk = f >> 3, ck = f & 7;         // K: 128 rows x 8 chunks
            cp16(base + (uint32_t)(rk * RBQ + ck * 16),
                 g_K + hoff + (size_t)(j0 + rk) * 64 + ck * 8);
            int rv = f >> 4, cv = f & 15;        // Vt: 64 rows x 16 chunks
            cp16(base + KT + (uint32_t)(rv * RBV + cv * 16),
                 g_Vt + hoff + (size_t)rv * 2048 + j0 + cv * 8);
        }
    };

    // Stage Q through buffer 0 (K area), pull to regs (2 m-frags/warp)
#pragma unroll
    for (int it = 0; it < 8; it++) {
        int f = tid + it * 128;
        int r = f >> 3, c = f & 7;
        cp16(sb + (uint32_t)(r * RBQ + c * 16),
             g_Q + hoff + (size_t)(mblk + r) * 64 + c * 8);
    }
    CP_COMMIT(); CP_WAIT(0);
    __syncthreads();
    uint32_t qf[2][4][4];
#pragma unroll
    for (int mf = 0; mf < 2; mf++)
#pragma unroll
        for (int kc = 0; kc < 4; kc++) {
            uint32_t off = (uint32_t)((w * 32 + mf * 16 + (lane & 15)) * RBQ
                         + kc * 32 + (lane >> 4) * 16);
            ldsm4(qf[mf][kc], sb + off);
        }
    __syncthreads();

    load_chunk(0, 0); CP_COMMIT();
    load_chunk(1, 1); CP_COMMIT();

    float O[2][8][4];
#pragma unroll
    for (int mf = 0; mf < 2; mf++)
#pragma unroll
        for (int g = 0; g < 8; g++)
#pragma unroll
            for (int i = 0; i < 4; i++) O[mf][g][i] = 0.0f;
    float lsum[2][2] = {{0.0f, 0.0f}, {0.0f, 0.0f}};

    const uint32_t mi = (uint32_t)(lane >> 3);
    const uint32_t prow = ((mi >> 1) << 3) + (lane & 7);
    const uint32_t pcol = (mi & 1) << 4;

#pragma unroll 1
    for (int ch = 0; ch < 16; ch++) {
        CP_WAIT(1);
        __syncthreads();
        const uint32_t tb = sb + (uint32_t)(ch & 1) * ASTG;

        // Fused per 16-column group: S -> ex2(f16x2) -> P -> PV.
        // K/V fragments loaded ONCE, used by both m-frags.
#pragma unroll
        for (int pc = 0; pc < 8; pc++) {
            float S[2][2][4];
#pragma unroll
            for (int mf = 0; mf < 2; mf++)
#pragma unroll
                for (int i = 0; i < 4; i++) { S[mf][0][i] = 0.0f; S[mf][1][i] = 0.0f; }
#pragma unroll
            for (int kc = 0; kc < 4; kc++) {
                uint32_t kb[4];
                ldsm4(kb, tb + (uint32_t)((pc * 16 + prow) * RBQ + kc * 32 + pcol));
#pragma unroll
                for (int mf = 0; mf < 2; mf++) {
                    mma16816(S[mf][0], qf[mf][kc], kb);
                    mma16816(S[mf][1], qf[mf][kc], kb + 2);
                }
            }
            uint32_t pa[2][4];
#pragma unroll
            for (int mf = 0; mf < 2; mf++) {
                pa[mf][0] = h2ex2(pack2h(S[mf][0][0], S[mf][0][1]));
                pa[mf][1] = h2ex2(pack2h(S[mf][0][2], S[mf][0][3]));
                pa[mf][2] = h2ex2(pack2h(S[mf][1][0], S[mf][1][1]));
                pa[mf][3] = h2ex2(pack2h(S[mf][1][2], S[mf][1][3]));
                float2 f0 = h22f2(pa[mf][0]), f1 = h22f2(pa[mf][1]);
                float2 f2 = h22f2(pa[mf][2]), f3 = h22f2(pa[mf][3]);
                lsum[mf][0] += f0.x + f0.y + f2.x + f2.y;
                lsum[mf][1] += f1.x + f1.y + f3.x + f3.y;
            }
#pragma unroll
            for (int vg = 0; vg < 4; vg++) {
                uint32_t vb[4];
                ldsm4(vb, tb + KT + (uint32_t)((vg * 16 + prow) * RBV + pc * 32 + pcol));
#pragma unroll
                for (int mf = 0; mf < 2; mf++) {
                    mma16816(O[mf][2 * vg],     pa[mf], vb);
                    mma16816(O[mf][2 * vg + 1], pa[mf], vb + 2);
                }
            }
        }
        __syncthreads();
        if (ch + 2 < 16) load_chunk(ch + 2, ch & 1);
        CP_COMMIT();
    }

    // Row sums over each quad, normalize, store X
#pragma unroll
    for (int mf = 0; mf < 2; mf++)
#pragma unroll
        for (int hf = 0; hf < 2; hf++) {
            lsum[mf][hf] += __shfl_xor_sync(0xffffffffu, lsum[mf][hf], 1, 4);
            lsum[mf][hf] += __shfl_xor_sync(0xffffffffu, lsum[mf][hf], 2, 4);
        }

    const int b = bh >> 4, h = bh & 15;
#pragma unroll
    for (int mf = 0; mf < 2; mf++) {
        const float inv0 = 1.0f / lsum[mf][0], inv1 = 1.0f / lsum[mf][1];
        const int m0 = mblk + w * 32 + mf * 16 + (lane >> 2);
#pragma unroll
        for (int gd = 0; gd < 8; gd++) {
            int cc = h * 64 + gd * 8 + 2 * (lane & 3);
            size_t o = (size_t)(b * 2048 + m0) * 1024 + cc;
            *(uint32_t*)(g_X + o) = pack2h(O[mf][gd][0] * inv0, O[mf][gd][1] * inv0);
            o = (size_t)(b * 2048 + m0 + 8) * 1024 + cc;
            *(uint32_t*)(g_X + o) = pack2h(O[mf][gd][2] * inv1, O[mf][gd][3] * inv1);
        }
    }
}

// ---------------------------------------------------------------------------
extern "C" void kernel_launch(void* const* d_in, const int* in_sizes, int n_in,
                              void* d_out, int out_size)
{
    const float* ref   = (const float*)d_in[0];
    const float* tgt   = (const float*)d_in[1];
    const float* Wq    = (const float*)d_in[2];
    const float* Wkv   = (const float*)d_in[3];
    const float* Wproj = (const float*)d_in[4];
    const float* bproj = (const float*)d_in[5];
    float* out = (float*)d_out;

    cudaFuncSetAttribute(gemm01,   cudaFuncAttributeMaxDynamicSharedMemorySize, GEMM_SMEM);
    cudaFuncSetAttribute(gemm2,    cudaFuncAttributeMaxDynamicSharedMemorySize, GEMM_SMEM);
    cudaFuncSetAttribute(attn_mma, cudaFuncAttributeMaxDynamicSharedMemorySize, ATTN_SMEM);

    prep_all<<<12288, 256>>>(tgt, ref, Wq, Wkv, Wproj);    // flat-packed, zero waste

    gemm01<<<dim3(24, 32), 256, GEMM_SMEM>>>();            // Q-proj + KV-proj merged
    attn_mma<<<dim3(16, 32), 128, ATTN_SMEM>>>();          // attention
    gemm2<<<dim3(8, 32), 256, GEMM_SMEM>>>(bproj, out);    // out-proj
}

// round 16
// speedup vs baseline: 1.1280x; 1.0727x over previous
#include <cuda_runtime.h>
#include <cuda_fp16.h>
#include <cstdint>

// Problem shape (fixed)
#define Bb   2
#define Hh   16
#define Mm   2048
#define Nn   2048
#define Ccon 1024
#define HD   64

#define QSCALE 0.18033688f   // 0.125 * log2(e); P = 2^(Q'.K)

// ---------------------------------------------------------------------------
// Device-global scratch (single fp16)
// ---------------------------------------------------------------------------
__device__ __align__(128) __half g_tgt[4194304];    // [b*M][C]
__device__ __align__(128) __half g_ref[4194304];    // [b*N][C]
__device__ __align__(128) __half g_Wq [1048576];    // [N][K] (transposed)
__device__ __align__(128) __half g_Wkv[2097152];    // [N][K]
__device__ __align__(128) __half g_Wp [1048576];    // [N][K]
__device__ __align__(128) __half g_Q [4194304];     // [bh][m][d] (x QSCALE)
__device__ __align__(128) __half g_K [4194304];     // [bh][n][d]
__device__ __align__(128) __half g_Vt[4194304];     // [bh][d][n]
__device__ __align__(128) __half g_X [4194304];     // [b*M][C]

// ---------------------------------------------------------------------------
// Helpers (plain sm_80+ PTX)
// ---------------------------------------------------------------------------
__device__ __forceinline__ uint32_t smem_u32(const void* p) {
    uint32_t a;
    asm("{ .reg .u64 t; cvta.to.shared.u64 t, %1; cvt.u32.u64 %0, t; }" : "=r"(a) : "l"(p));
    return a;
}
__device__ __forceinline__ void cp16(uint32_t s, const void* g) {
    asm volatile("cp.async.cg.shared.global [%0], [%1], 16;" :: "r"(s), "l"(g));
}
#define CP_COMMIT() asm volatile("cp.async.commit_group;" ::: "memory")
#define CP_WAIT(n)  asm volatile("cp.async.wait_group %0;" :: "n"(n) : "memory")

__device__ __forceinline__ void ldsm4(uint32_t r[4], uint32_t a) {
    asm volatile("ldmatrix.sync.aligned.m8n8.x4.shared.b16 {%0,%1,%2,%3}, [%4];"
        : "=r"(r[0]), "=r"(r[1]), "=r"(r[2]), "=r"(r[3]) : "r"(a));
}
__device__ __forceinline__ void mma16816(float c[4], const uint32_t a[4], const uint32_t b[2]) {
    asm volatile("mma.sync.aligned.m16n8k16.row.col.f32.f16.f16.f32 "
        "{%0,%1,%2,%3}, {%4,%5,%6,%7}, {%8,%9}, {%0,%1,%2,%3};"
        : "+f"(c[0]), "+f"(c[1]), "+f"(c[2]), "+f"(c[3])
        : "r"(a[0]), "r"(a[1]), "r"(a[2]), "r"(a[3]), "r"(b[0]), "r"(b[1]));
}
__device__ __forceinline__ uint32_t pack2h(float a, float b) {
    __half2 v = __floats2half2_rn(a, b);
    return *(uint32_t*)&v;
}
__device__ __forceinline__ uint32_t h2ex2(uint32_t x) {
    uint32_t r;
    asm("ex2.approx.f16x2 %0, %1;" : "=r"(r) : "r"(x));
    return r;
}
__device__ __forceinline__ float2 h22f2(uint32_t x) {
    __half2 h = *(__half2*)&x;
    return __half22float2(h);
}

// ---------------------------------------------------------------------------
// Prep: ONE flat-packed launch, zero wasted blocks (R15 exact).
// ---------------------------------------------------------------------------
__global__ __launch_bounds__(256) void prep_all(
    const float* __restrict__ tgt, const float* __restrict__ ref,
    const float* __restrict__ Wq, const float* __restrict__ Wkv,
    const float* __restrict__ Wp)
{
    const int blk = blockIdx.x;
    if (blk < 8192) {
        int i = blk * 256 + threadIdx.x;
        const bool second = i >= 1048576;
        const float* in = second ? ref : tgt;
        __half* o = second ? g_ref : g_tgt;
        int j = second ? i - 1048576 : i;
        float4 v = ((const float4*)in)[j];
        uint2 hv = { pack2h(v.x, v.y), pack2h(v.z, v.w) };
        *(uint2*)(o + (size_t)j * 4) = hv;
        return;
    }
    int t = blk - 8192;
    const float* W;
    __half* o;
    int Ntot, tt;
    if (t < 1024)      { W = Wq;  o = g_Wq;  Ntot = 1024; tt = t; }
    else if (t < 3072) { W = Wkv; o = g_Wkv; Ntot = 2048; tt = t - 1024; }
    else               { W = Wp;  o = g_Wp;  Ntot = 1024; tt = t - 3072; }
    const int ntiles = Ntot >> 5;
    const int n0 = (tt % ntiles) * 32, k0 = (tt / ntiles) * 32;

    __shared__ float tb[32][33];
    int x = threadIdx.x & 31, y = threadIdx.x >> 5;
#pragma unroll
    for (int i = 0; i < 32; i += 8)
        tb[y + i][x] = W[(size_t)(k0 + y + i) * Ntot + n0 + x];
    __syncthreads();
#pragma unroll
    for (int i = 0; i < 32; i += 8)
        o[(size_t)(n0 + y + i) * 1024 + k0 + x] = __float2half_rn(tb[x][y + i]);
}

// ---------------------------------------------------------------------------
// GEMM core: 128x128 tile, 4 warps (2x2, each 64x64), K-stage 32, 4-stage
// cp.async pipeline, 2 CTAs/SM. Per kc: 8 ldsm -> 32 MMAs (ILP 4x vs R15).
// ---------------------------------------------------------------------------
#define RB     80                         // smem row bytes (32 halves + pad)
#define ATILE  (128 * RB)                 // 10240
#define BTILE  (128 * RB)                 // 10240
#define GSTG   (ATILE + BTILE)            // 20480
#define GEMM_SMEM (4 * GSTG)              // 81920

__device__ __forceinline__ void gemm_core(
    float acc[4][8][4],
    const __half* __restrict__ A, const __half* __restrict__ Bw,
    int bm, int bn, uint32_t sb)
{
    const int tid = threadIdx.x, lane = tid & 31, w = tid >> 5;
    const int wm = w >> 1, wn = w & 1;     // 2 x 2 warps, warp tile 64x64

    auto load_stage = [&](int s, int buf) {
        const int k0 = s * 32;
        const uint32_t base = sb + (uint32_t)buf * GSTG;
#pragma unroll
        for (int it = 0; it < 4; it++) {       // A: 128 rows x 4 chunks, 128 thr
            int f = tid + it * 128;
            int r = f >> 2, c = f & 3;
            cp16(base + (uint32_t)(r * RB + c * 16),
                 A + (size_t)(bm + r) * 1024 + k0 + c * 8);
        }
#pragma unroll
        for (int it = 0; it < 4; it++) {       // B: 128 rows x 4 chunks
            int f = tid + it * 128;
            int r = f >> 2, c = f & 3;
            cp16(base + ATILE + (uint32_t)(r * RB + c * 16),
                 Bw + (size_t)(bn + r) * 1024 + k0 + c * 8);
        }
    };

#pragma unroll
    for (int i = 0; i < 4; i++)
#pragma unroll
        for (int j = 0; j < 8; j++)
#pragma unroll
            for (int k = 0; k < 4; k++) acc[i][j][k] = 0.0f;

    load_stage(0, 0); CP_COMMIT();
    load_stage(1, 1); CP_COMMIT();
    load_stage(2, 2); CP_COMMIT();

    const uint32_t mi = (uint32_t)(lane >> 3);
    const uint32_t prow = ((mi >> 1) << 3) + (lane & 7);
    const uint32_t pcol = (mi & 1) << 4;

#pragma unroll 1
    for (int s = 0; s < 32; s++) {
        CP_WAIT(2);
        __syncthreads();
        if (s + 3 < 32) load_stage(s + 3, (s + 3) & 3);
        CP_COMMIT();
        const uint32_t tb = sb + (uint32_t)(s & 3) * GSTG;
#pragma unroll
        for (int kc = 0; kc < 2; kc++) {
            uint32_t ah[4][4], bq[4][4];
#pragma unroll
            for (int mf = 0; mf < 4; mf++) {
                uint32_t off = (uint32_t)((wm * 64 + mf * 16 + (lane & 15)) * RB
                             + kc * 32 + (lane >> 4) * 16);
                ldsm4(ah[mf], tb + off);
            }
#pragma unroll
            for (int np = 0; np < 4; np++) {
                uint32_t off = (uint32_t)((wn * 64 + np * 16 + prow) * RB
                             + kc * 32 + pcol);
                ldsm4(bq[np], tb + ATILE + off);
            }
#pragma unroll
            for (int mf = 0; mf < 4; mf++)
#pragma unroll
                for (int np = 0; np < 4; np++) {
                    mma16816(acc[mf][2 * np],     ah[mf], bq[np]);
                    mma16816(acc[mf][2 * np + 1], ah[mf], bq[np] + 2);
                }
        }
    }
}

// Merged Q-proj + KV-proj: grid (24, 32), 128 thr. x<8 -> Q, else KV.
__global__ __launch_bounds__(128, 2) void gemm01() {
    extern __shared__ __align__(16) char sm[];
    const uint32_t sb = smem_u32(sm);
    const int tid = threadIdx.x, lane = tid & 31, w = tid >> 5;
    const int wm = w >> 1, wn = w & 1;
    const bool qm = blockIdx.x < 8;
    const int bm = blockIdx.y * 128;
    const int bn = (qm ? blockIdx.x : blockIdx.x - 8) * 128;

    float acc[4][8][4];
    gemm_core(acc, qm ? g_tgt : g_ref, qm ? g_Wq : g_Wkv, bm, bn, sb);

#pragma unroll
    for (int mf = 0; mf < 4; mf++)
#pragma unroll
        for (int nf = 0; nf < 8; nf++) {
            int r0 = bm + wm * 64 + mf * 16 + (lane >> 2);
            int cc = bn + wn * 64 + nf * 8 + 2 * (lane & 3);
            float* a = acc[mf][nf];
#pragma unroll
            for (int hf = 0; hf < 2; hf++) {
                int r = r0 + hf * 8;
                float v0 = a[hf * 2], v1 = a[hf * 2 + 1];
                int b = r >> 11, row = r & 2047;
                if (qm) {
                    int h = cc >> 6, d = cc & 63;
                    size_t o = ((size_t)((b * 16 + h) * 2048 + row)) * 64 + d;
                    *(uint32_t*)(g_Q + o) = pack2h(v0 * QSCALE, v1 * QSCALE);
                } else if (cc < 1024) {
                    int h = cc >> 6, d = cc & 63;
                    size_t o = ((size_t)((b * 16 + h) * 2048 + row)) * 64 + d;
                    *(uint32_t*)(g_K + o) = pack2h(v0, v1);
                } else {
                    int cc2 = cc - 1024, h = cc2 >> 6, d = cc2 & 63;
                    size_t o = ((size_t)((b * 16 + h) * 64 + d)) * 2048 + row;
                    g_Vt[o]        = __float2half_rn(v0);
                    g_Vt[o + 2048] = __float2half_rn(v1);
                }
            }
        }
}

// Output projection: X@Wp + bias -> out (fp32). grid (8, 32), 128 thr.
__global__ __launch_bounds__(128, 2) void gemm2(const float* __restrict__ bias,
                                                float* __restrict__ out) {
    extern __shared__ __align__(16) char sm[];
    const uint32_t sb = smem_u32(sm);
    const int tid = threadIdx.x, lane = tid & 31, w = tid >> 5;
    const int wm = w >> 1, wn = w & 1;
    const int bm = blockIdx.y * 128, bn = blockIdx.x * 128;

    float acc[4][8][4];
    gemm_core(acc, g_X, g_Wp, bm, bn, sb);

#pragma unroll
    for (int mf = 0; mf < 4; mf++)
#pragma unroll
        for (int nf = 0; nf < 8; nf++) {
            int r0 = bm + wm * 64 + mf * 16 + (lane >> 2);
            int cc = bn + wn * 64 + nf * 8 + 2 * (lane & 3);
            float* a = acc[mf][nf];
#pragma unroll
            for (int hf = 0; hf < 2; hf++) {
                int r = r0 + hf * 8;
                float2 ov = { a[hf * 2] + bias[cc], a[hf * 2 + 1] + bias[cc + 1] };
                *(float2*)(out + (size_t)r * 1024 + cc) = ov;
            }
        }
}

// ---------------------------------------------------------------------------
// Flash attention (R11/R15 exact): 4 warps x 32 q-rows (128 thr),
// frag-sharing, f16x2 exp. N chunks of 128, 2-stage pipeline, (128,2).
// ---------------------------------------------------------------------------
#define RBQ   144                           // 64 halves + 16B pad
#define RBV   272                           // 128 halves + 16B pad
#define KT    (128 * RBQ)                   // 18432
#define VT    (64 * RBV)                    // 17408
#define ASTG  (KT + VT)                     // 35840
#define ATTN_SMEM (2 * ASTG)                // 71680

__global__ __launch_bounds__(128, 2) void attn_mma() {
    extern __shared__ __align__(16) char sm[];
    const uint32_t sb = smem_u32(sm);
    const int tid = threadIdx.x, lane = tid & 31, w = tid >> 5;   // 4 warps
    const int bh = blockIdx.y, mblk = blockIdx.x * 128;
    const size_t hoff = (size_t)bh * 2048 * 64;

    auto load_chunk = [&](int ch, int buf) {
        const int j0 = ch * 128;
        const uint32_t base = sb + (uint32_t)buf * ASTG;
#pragma unroll
        for (int it = 0; it < 8; it++) {
            int f = tid + it * 128;              // 0..1023
            int rk = f >> 3, ck = f & 7;         // K: 128 rows x 8 chunks
            cp16(base + (uint32_t)(rk * RBQ + ck * 16),
                 g_K + hoff + (size_t)(j0 + rk) * 64 + ck * 8);
            int rv = f >> 4, cv = f & 15;        // Vt: 64 rows x 16 chunks
            cp16(base + KT + (uint32_t)(rv * RBV + cv * 16),
                 g_Vt + hoff + (size_t)rv * 2048 + j0 + cv * 8);
        }
    };

    // Stage Q through buffer 0 (K area), pull to regs (2 m-frags/warp)
#pragma unroll
    for (int it = 0; it < 8; it++) {
        int f = tid + it * 128;
        int r = f >> 3, c = f & 7;
        cp16(sb + (uint32_t)(r * RBQ + c * 16),
             g_Q + hoff + (size_t)(mblk + r) * 64 + c * 8);
    }
    CP_COMMIT(); CP_WAIT(0);
    __syncthreads();
    uint32_t qf[2][4][4];
#pragma unroll
    for (int mf = 0; mf < 2; mf++)
#pragma unroll
        for (int kc = 0; kc < 4; kc++) {
            uint32_t off = (uint32_t)((w * 32 + mf * 16 + (lane & 15)) * RBQ
                         + kc * 32 + (lane >> 4) * 16);
            ldsm4(qf[mf][kc], sb + off);
        }
    __syncthreads();

    load_chunk(0, 0); CP_COMMIT();
    load_chunk(1, 1); CP_COMMIT();

    float O[2][8][4];
#pragma unroll
    for (int mf = 0; mf < 2; mf++)
#pragma unroll
        for (int g = 0; g < 8; g++)
#pragma unroll
            for (int i = 0; i < 4; i++) O[mf][g][i] = 0.0f;
    float lsum[2][2] = {{0.0f, 0.0f}, {0.0f, 0.0f}};

    const uint32_t mi = (uint32_t)(lane >> 3);
    const uint32_t prow = ((mi >> 1) << 3) + (lane & 7);
    const uint32_t pcol = (mi & 1) << 4;

#pragma unroll 1
    for (int ch = 0; ch < 16; ch++) {
        CP_WAIT(1);
        __syncthreads();
        const uint32_t tb = sb + (uint32_t)(ch & 1) * ASTG;

        // Fused per 16-column group: S -> ex2(f16x2) -> P -> PV.
#pragma unroll
        for (int pc = 0; pc < 8; pc++) {
            float S[2][2][4];
#pragma unroll
            for (int mf = 0; mf < 2; mf++)
#pragma unroll
                for (int i = 0; i < 4; i++) { S[mf][0][i] = 0.0f; S[mf][1][i] = 0.0f; }
#pragma unroll
            for (int kc = 0; kc < 4; kc++) {
                uint32_t kb[4];
                ldsm4(kb, tb + (uint32_t)((pc * 16 + prow) * RBQ + kc * 32 + pcol));
#pragma unroll
                for (int mf = 0; mf < 2; mf++) {
                    mma16816(S[mf][0], qf[mf][kc], kb);
                    mma16816(S[mf][1], qf[mf][kc], kb + 2);
                }
            }
            uint32_t pa[2][4];
#pragma unroll
            for (int mf = 0; mf < 2; mf++) {
                pa[mf][0] = h2ex2(pack2h(S[mf][0][0], S[mf][0][1]));
                pa[mf][1] = h2ex2(pack2h(S[mf][0][2], S[mf][0][3]));
                pa[mf][2] = h2ex2(pack2h(S[mf][1][0], S[mf][1][1]));
                pa[mf][3] = h2ex2(pack2h(S[mf][1][2], S[mf][1][3]));
                float2 f0 = h22f2(pa[mf][0]), f1 = h22f2(pa[mf][1]);
                float2 f2 = h22f2(pa[mf][2]), f3 = h22f2(pa[mf][3]);
                lsum[mf][0] += f0.x + f0.y + f2.x + f2.y;
                lsum[mf][1] += f1.x + f1.y + f3.x + f3.y;
            }
#pragma unroll
            for (int vg = 0; vg < 4; vg++) {
                uint32_t vb[4];
                ldsm4(vb, tb + KT + (uint32_t)((vg * 16 + prow) * RBV + pc * 32 + pcol));
#pragma unroll
                for (int mf = 0; mf < 2; mf++) {
                    mma16816(O[mf][2 * vg],     pa[mf], vb);
                    mma16816(O[mf][2 * vg + 1], pa[mf], vb + 2);
                }
            }
        }
        __syncthreads();
        if (ch + 2 < 16) load_chunk(ch + 2, ch & 1);
        CP_COMMIT();
    }

    // Row sums over each quad, normalize, store X
#pragma unroll
    for (int mf = 0; mf < 2; mf++)
#pragma unroll
        for (int hf = 0; hf < 2; hf++) {
            lsum[mf][hf] += __shfl_xor_sync(0xffffffffu, lsum[mf][hf], 1, 4);
            lsum[mf][hf] += __shfl_xor_sync(0xffffffffu, lsum[mf][hf], 2, 4);
        }

    const int b = bh >> 4, h = bh & 15;
#pragma unroll
    for (int mf = 0; mf < 2; mf++) {
        const float inv0 = 1.0f / lsum[mf][0], inv1 = 1.0f / lsum[mf][1];
        const int m0 = mblk + w * 32 + mf * 16 + (lane >> 2);
#pragma unroll
        for (int gd = 0; gd < 8; gd++) {
            int cc = h * 64 + gd * 8 + 2 * (lane & 3);
            size_t o = (size_t)(b * 2048 + m0) * 1024 + cc;
            *(uint32_t*)(g_X + o) = pack2h(O[mf][gd][0] * inv0, O[mf][gd][1] * inv0);
            o = (size_t)(b * 2048 + m0 + 8) * 1024 + cc;
            *(uint32_t*)(g_X + o) = pack2h(O[mf][gd][2] * inv1, O[mf][gd][3] * inv1);
        }
    }
}

// ---------------------------------------------------------------------------
extern "C" void kernel_launch(void* const* d_in, const int* in_sizes, int n_in,
                              void* d_out, int out_size)
{
    const float* ref   = (const float*)d_in[0];
    const float* tgt   = (const float*)d_in[1];
    const float* Wq    = (const float*)d_in[2];
    const float* Wkv   = (const float*)d_in[3];
    const float* Wproj = (const float*)d_in[4];
    const float* bproj = (const float*)d_in[5];
    float* out = (float*)d_out;

    cudaFuncSetAttribute(gemm01,   cudaFuncAttributeMaxDynamicSharedMemorySize, GEMM_SMEM);
    cudaFuncSetAttribute(gemm2,    cudaFuncAttributeMaxDynamicSharedMemorySize, GEMM_SMEM);
    cudaFuncSetAttribute(attn_mma, cudaFuncAttributeMaxDynamicSharedMemorySize, ATTN_SMEM);

    prep_all<<<12288, 256>>>(tgt, ref, Wq, Wkv, Wproj);    // flat-packed, zero waste

    gemm01<<<dim3(24, 32), 128, GEMM_SMEM>>>();            // Q-proj + KV-proj merged
    attn_mma<<<dim3(16, 32), 128, ATTN_SMEM>>>();          // attention
    gemm2<<<dim3(8, 32), 128, GEMM_SMEM>>>(bproj, out);    // out-proj
}

// round 17
// speedup vs baseline: 1.1584x; 1.0270x over previous
#include <cuda_runtime.h>
#include <cuda_fp16.h>
#include <cstdint>

// Problem shape (fixed)
#define Bb   2
#define Hh   16
#define Mm   2048
#define Nn   2048
#define Ccon 1024
#define HD   64

#define QSCALE 0.18033688f   // 0.125 * log2(e); P = 2^(Q'.K)

// ---------------------------------------------------------------------------
// Device-global scratch (single fp16)
// ---------------------------------------------------------------------------
__device__ __align__(128) __half g_tgt[4194304];    // [b*M][C]
__device__ __align__(128) __half g_ref[4194304];    // [b*N][C]
__device__ __align__(128) __half g_Wq [1048576];    // [N][K] (transposed)
__device__ __align__(128) __half g_Wkv[2097152];    // [N][K]
__device__ __align__(128) __half g_Wp [1048576];    // [N][K]
__device__ __align__(128) __half g_Q [4194304];     // [bh][m][d] (x QSCALE)
__device__ __align__(128) __half g_K [4194304];     // [bh][n][d]
__device__ __align__(128) __half g_Vt[4194304];     // [bh][d][n]
__device__ __align__(128) __half g_X [4194304];     // [b*M][C]

// ---------------------------------------------------------------------------
// Helpers (plain sm_80+ PTX)
// ---------------------------------------------------------------------------
__device__ __forceinline__ uint32_t smem_u32(const void* p) {
    uint32_t a;
    asm("{ .reg .u64 t; cvta.to.shared.u64 t, %1; cvt.u32.u64 %0, t; }" : "=r"(a) : "l"(p));
    return a;
}
__device__ __forceinline__ void cp16(uint32_t s, const void* g) {
    asm volatile("cp.async.cg.shared.global [%0], [%1], 16;" :: "r"(s), "l"(g));
}
#define CP_COMMIT() asm volatile("cp.async.commit_group;" ::: "memory")
#define CP_WAIT(n)  asm volatile("cp.async.wait_group %0;" :: "n"(n) : "memory")

__device__ __forceinline__ void ldsm4(uint32_t r[4], uint32_t a) {
    asm volatile("ldmatrix.sync.aligned.m8n8.x4.shared.b16 {%0,%1,%2,%3}, [%4];"
        : "=r"(r[0]), "=r"(r[1]), "=r"(r[2]), "=r"(r[3]) : "r"(a));
}
__device__ __forceinline__ void mma16816(float c[4], const uint32_t a[4], const uint32_t b[2]) {
    asm volatile("mma.sync.aligned.m16n8k16.row.col.f32.f16.f16.f32 "
        "{%0,%1,%2,%3}, {%4,%5,%6,%7}, {%8,%9}, {%0,%1,%2,%3};"
        : "+f"(c[0]), "+f"(c[1]), "+f"(c[2]), "+f"(c[3])
        : "r"(a[0]), "r"(a[1]), "r"(a[2]), "r"(a[3]), "r"(b[0]), "r"(b[1]));
}
__device__ __forceinline__ uint32_t pack2h(float a, float b) {
    __half2 v = __floats2half2_rn(a, b);
    return *(uint32_t*)&v;
}
__device__ __forceinline__ uint32_t h2ex2(uint32_t x) {
    uint32_t r;
    asm("ex2.approx.f16x2 %0, %1;" : "=r"(r) : "r"(x));
    return r;
}
__device__ __forceinline__ float2 h22f2(uint32_t x) {
    __half2 h = *(__half2*)&x;
    return __half22float2(h);
}

// ---------------------------------------------------------------------------
// Prep: ONE flat-packed launch, zero wasted blocks (R15 exact).
// ---------------------------------------------------------------------------
__global__ __launch_bounds__(256) void prep_all(
    const float* __restrict__ tgt, const float* __restrict__ ref,
    const float* __restrict__ Wq, const float* __restrict__ Wkv,
    const float* __restrict__ Wp)
{
    const int blk = blockIdx.x;
    if (blk < 8192) {
        int i = blk * 256 + threadIdx.x;
        const bool second = i >= 1048576;
        const float* in = second ? ref : tgt;
        __half* o = second ? g_ref : g_tgt;
        int j = second ? i - 1048576 : i;
        float4 v = ((const float4*)in)[j];
        uint2 hv = { pack2h(v.x, v.y), pack2h(v.z, v.w) };
        *(uint2*)(o + (size_t)j * 4) = hv;
        return;
    }
    int t = blk - 8192;
    const float* W;
    __half* o;
    int Ntot, tt;
    if (t < 1024)      { W = Wq;  o = g_Wq;  Ntot = 1024; tt = t; }
    else if (t < 3072) { W = Wkv; o = g_Wkv; Ntot = 2048; tt = t - 1024; }
    else               { W = Wp;  o = g_Wp;  Ntot = 1024; tt = t - 3072; }
    const int ntiles = Ntot >> 5;
    const int n0 = (tt % ntiles) * 32, k0 = (tt / ntiles) * 32;

    __shared__ float tb[32][33];
    int x = threadIdx.x & 31, y = threadIdx.x >> 5;
#pragma unroll
    for (int i = 0; i < 32; i += 8)
        tb[y + i][x] = W[(size_t)(k0 + y + i) * Ntot + n0 + x];
    __syncthreads();
#pragma unroll
    for (int i = 0; i < 32; i += 8)
        o[(size_t)(n0 + y + i) * 1024 + k0 + x] = __float2half_rn(tb[x][y + i]);
}

// ---------------------------------------------------------------------------
// GEMM core (R16 exact): 128x128 tile, 4 warps (2x2, each 64x64), K-stage 32,
// 4-stage cp.async pipeline, 2 CTAs/SM.
// ---------------------------------------------------------------------------
#define RB     80                         // smem row bytes (32 halves + pad)
#define ATILE  (128 * RB)                 // 10240
#define BTILE  (128 * RB)                 // 10240
#define GSTG   (ATILE + BTILE)            // 20480
#define GEMM_SMEM (4 * GSTG)              // 81920

__device__ __forceinline__ void gemm_core(
    float acc[4][8][4],
    const __half* __restrict__ A, const __half* __restrict__ Bw,
    int bm, int bn, uint32_t sb)
{
    const int tid = threadIdx.x, lane = tid & 31, w = tid >> 5;
    const int wm = w >> 1, wn = w & 1;     // 2 x 2 warps, warp tile 64x64

    auto load_stage = [&](int s, int buf) {
        const int k0 = s * 32;
        const uint32_t base = sb + (uint32_t)buf * GSTG;
#pragma unroll
        for (int it = 0; it < 4; it++) {
            int f = tid + it * 128;
            int r = f >> 2, c = f & 3;
            cp16(base + (uint32_t)(r * RB + c * 16),
                 A + (size_t)(bm + r) * 1024 + k0 + c * 8);
        }
#pragma unroll
        for (int it = 0; it < 4; it++) {
            int f = tid + it * 128;
            int r = f >> 2, c = f & 3;
            cp16(base + ATILE + (uint32_t)(r * RB + c * 16),
                 Bw + (size_t)(bn + r) * 1024 + k0 + c * 8);
        }
    };

#pragma unroll
    for (int i = 0; i < 4; i++)
#pragma unroll
        for (int j = 0; j < 8; j++)
#pragma unroll
            for (int k = 0; k < 4; k++) acc[i][j][k] = 0.0f;

    load_stage(0, 0); CP_COMMIT();
    load_stage(1, 1); CP_COMMIT();
    load_stage(2, 2); CP_COMMIT();

    const uint32_t mi = (uint32_t)(lane >> 3);
    const uint32_t prow = ((mi >> 1) << 3) + (lane & 7);
    const uint32_t pcol = (mi & 1) << 4;

#pragma unroll 1
    for (int s = 0; s < 32; s++) {
        CP_WAIT(2);
        __syncthreads();
        if (s + 3 < 32) load_stage(s + 3, (s + 3) & 3);
        CP_COMMIT();
        const uint32_t tb = sb + (uint32_t)(s & 3) * GSTG;
#pragma unroll
        for (int kc = 0; kc < 2; kc++) {
            uint32_t ah[4][4], bq[4][4];
#pragma unroll
            for (int mf = 0; mf < 4; mf++) {
                uint32_t off = (uint32_t)((wm * 64 + mf * 16 + (lane & 15)) * RB
                             + kc * 32 + (lane >> 4) * 16);
                ldsm4(ah[mf], tb + off);
            }
#pragma unroll
            for (int np = 0; np < 4; np++) {
                uint32_t off = (uint32_t)((wn * 64 + np * 16 + prow) * RB
                             + kc * 32 + pcol);
                ldsm4(bq[np], tb + ATILE + off);
            }
#pragma unroll
            for (int mf = 0; mf < 4; mf++)
#pragma unroll
                for (int np = 0; np < 4; np++) {
                    mma16816(acc[mf][2 * np],     ah[mf], bq[np]);
                    mma16816(acc[mf][2 * np + 1], ah[mf], bq[np] + 2);
                }
        }
    }
}

// Merged Q-proj + KV-proj: grid (24, 32), 128 thr. x<8 -> Q, else KV.
// V-half CTAs (bn>=1024 in KV space) use a smem transpose for coalesced
// g_Vt stores (identical values; replaces 2B scattered STG).
__global__ __launch_bounds__(128, 2) void gemm01() {
    extern __shared__ __align__(16) char sm[];
    const uint32_t sb = smem_u32(sm);
    const int tid = threadIdx.x, lane = tid & 31, w = tid >> 5;
    const int wm = w >> 1, wn = w & 1;
    const bool qm = blockIdx.x < 8;
    const int bm = blockIdx.y * 128;
    const int bn = (qm ? blockIdx.x : blockIdx.x - 8) * 128;

    float acc[4][8][4];
    gemm_core(acc, qm ? g_tgt : g_ref, qm ? g_Wq : g_Wkv, bm, bn, sb);

    const int b = bm >> 11;
    const int n0 = bm & 2047;

    if (!qm && bn >= 1024) {
        // ----- V path: transpose through smem, coalesced uint4 stores -----
        const int TP = 136;                     // halves per smem row (pad)
        __half* st = (__half*)sm;               // safe: trailing warps only
                                                // touch stage buffer 3 (61KB+)
#pragma unroll
        for (int mf = 0; mf < 4; mf++)
#pragma unroll
            for (int nf = 0; nf < 8; nf++) {
                int row = wm * 64 + mf * 16 + (lane >> 2);
                int col = wn * 64 + nf * 8 + 2 * (lane & 3);
                float* a = acc[mf][nf];
#pragma unroll
                for (int hf = 0; hf < 2; hf++) {
                    int r = row + hf * 8;
                    st[col * TP + r]       = __float2half_rn(a[hf * 2]);
                    st[(col + 1) * TP + r] = __float2half_rn(a[hf * 2 + 1]);
                }
            }
        __syncthreads();
        const int cc0 = bn - 1024;
#pragma unroll
        for (int it = 0; it < 16; it++) {
            int i = tid + it * 128;
            int drow = i >> 4, seg = i & 15;
            int cc2 = cc0 + drow, h = cc2 >> 6, d = cc2 & 63;
            uint4 v = *(uint4*)&st[drow * TP + seg * 8];
            *(uint4*)(g_Vt + ((size_t)((b * 16 + h) * 64 + d)) * 2048 + n0 + seg * 8) = v;
        }
        return;
    }

    // ----- Q / K paths (element-wise, as R16) -----
#pragma unroll
    for (int mf = 0; mf < 4; mf++)
#pragma unroll
        for (int nf = 0; nf < 8; nf++) {
            int r0 = bm + wm * 64 + mf * 16 + (lane >> 2);
            int cc = bn + wn * 64 + nf * 8 + 2 * (lane & 3);
            float* a = acc[mf][nf];
#pragma unroll
            for (int hf = 0; hf < 2; hf++) {
                int r = r0 + hf * 8;
                float v0 = a[hf * 2], v1 = a[hf * 2 + 1];
                int row = r & 2047;
                int h = cc >> 6, d = cc & 63;
                if (qm) {
                    size_t o = ((size_t)((b * 16 + h) * 2048 + row)) * 64 + d;
                    *(uint32_t*)(g_Q + o) = pack2h(v0 * QSCALE, v1 * QSCALE);
                } else {
                    size_t o = ((size_t)((b * 16 + h) * 2048 + row)) * 64 + d;
                    *(uint32_t*)(g_K + o) = pack2h(v0, v1);
                }
            }
        }
}

// Output projection: X@Wp + bias -> out (fp32). grid (8, 32), 128 thr.
__global__ __launch_bounds__(128, 2) void gemm2(const float* __restrict__ bias,
                                                float* __restrict__ out) {
    extern __shared__ __align__(16) char sm[];
    const uint32_t sb = smem_u32(sm);
    const int tid = threadIdx.x, lane = tid & 31, w = tid >> 5;
    const int wm = w >> 1, wn = w & 1;
    const int bm = blockIdx.y * 128, bn = blockIdx.x * 128;

    float acc[4][8][4];
    gemm_core(acc, g_X, g_Wp, bm, bn, sb);

#pragma unroll
    for (int mf = 0; mf < 4; mf++)
#pragma unroll
        for (int nf = 0; nf < 8; nf++) {
            int r0 = bm + wm * 64 + mf * 16 + (lane >> 2);
            int cc = bn + wn * 64 + nf * 8 + 2 * (lane & 3);
            float* a = acc[mf][nf];
#pragma unroll
            for (int hf = 0; hf < 2; hf++) {
                int r = r0 + hf * 8;
                float2 ov = { a[hf * 2] + bias[cc], a[hf * 2 + 1] + bias[cc + 1] };
                *(float2*)(out + (size_t)r * 1024 + cc) = ov;
            }
        }
}

// ---------------------------------------------------------------------------
// Flash attention: 4 warps x 32 q-rows (128 thr), frag-sharing, f16x2 exp.
// N chunks of 128. NEW: 3-stage cp.async pipeline, loads issued BEFORE
// compute, ONE __syncthreads per chunk (GEMM-loop structure). 2 CTAs/SM.
// ---------------------------------------------------------------------------
#define RBQ   144                           // 64 halves + 16B pad
#define RBV   272                           // 128 halves + 16B pad
#define KT    (128 * RBQ)                   // 18432
#define VT    (64 * RBV)                    // 17408
#define ASTG  (KT + VT)                     // 35840
#define ATTN_SMEM (3 * ASTG)                // 107520

__global__ __launch_bounds__(128, 2) void attn_mma() {
    extern __shared__ __align__(16) char sm[];
    const uint32_t sb = smem_u32(sm);
    const int tid = threadIdx.x, lane = tid & 31, w = tid >> 5;   // 4 warps
    const int bh = blockIdx.y, mblk = blockIdx.x * 128;
    const size_t hoff = (size_t)bh * 2048 * 64;

    auto load_chunk = [&](int ch, int buf) {
        const int j0 = ch * 128;
        const uint32_t base = sb + (uint32_t)buf * ASTG;
#pragma unroll
        for (int it = 0; it < 8; it++) {
            int f = tid + it * 128;              // 0..1023
            int rk = f >> 3, ck = f & 7;         // K: 128 rows x 8 chunks
            cp16(base + (uint32_t)(rk * RBQ + ck * 16),
                 g_K + hoff + (size_t)(j0 + rk) * 64 + ck * 8);
            int rv = f >> 4, cv = f & 15;        // Vt: 64 rows x 16 chunks
            cp16(base + KT + (uint32_t)(rv * RBV + cv * 16),
                 g_Vt + hoff + (size_t)rv * 2048 + j0 + cv * 8);
        }
    };

    // Stage Q through buffer 0 (K area), pull to regs (2 m-frags/warp)
#pragma unroll
    for (int it = 0; it < 8; it++) {
        int f = tid + it * 128;
        int r = f >> 3, c = f & 7;
        cp16(sb + (uint32_t)(r * RBQ + c * 16),
             g_Q + hoff + (size_t)(mblk + r) * 64 + c * 8);
    }
    CP_COMMIT(); CP_WAIT(0);
    __syncthreads();
    uint32_t qf[2][4][4];
#pragma unroll
    for (int mf = 0; mf < 2; mf++)
#pragma unroll
        for (int kc = 0; kc < 4; kc++) {
            uint32_t off = (uint32_t)((w * 32 + mf * 16 + (lane & 15)) * RBQ
                         + kc * 32 + (lane >> 4) * 16);
            ldsm4(qf[mf][kc], sb + off);
        }
    __syncthreads();

    load_chunk(0, 0); CP_COMMIT();
    load_chunk(1, 1); CP_COMMIT();

    float O[2][8][4];
#pragma unroll
    for (int mf = 0; mf < 2; mf++)
#pragma unroll
        for (int g = 0; g < 8; g++)
#pragma unroll
            for (int i = 0; i < 4; i++) O[mf][g][i] = 0.0f;
    float lsum[2][2] = {{0.0f, 0.0f}, {0.0f, 0.0f}};

    const uint32_t mi = (uint32_t)(lane >> 3);
    const uint32_t prow = ((mi >> 1) << 3) + (lane & 7);
    const uint32_t pcol = (mi & 1) << 4;

#pragma unroll 1
    for (int ch = 0; ch < 16; ch++) {
        CP_WAIT(1);
        __syncthreads();        // all warps done with ch-1's buffer
        if (ch + 2 < 16) load_chunk(ch + 2, (ch + 2) % 3);
        CP_COMMIT();
        const uint32_t tb = sb + (uint32_t)(ch % 3) * ASTG;

        // Fused per 16-column group: S -> ex2(f16x2) -> P -> PV.
#pragma unroll
        for (int pc = 0; pc < 8; pc++) {
            float S[2][2][4];
#pragma unroll
            for (int mf = 0; mf < 2; mf++)
#pragma unroll
                for (int i = 0; i < 4; i++) { S[mf][0][i] = 0.0f; S[mf][1][i] = 0.0f; }
#pragma unroll
            for (int kc = 0; kc < 4; kc++) {
                uint32_t kb[4];
                ldsm4(kb, tb + (uint32_t)((pc * 16 + prow) * RBQ + kc * 32 + pcol));
#pragma unroll
                for (int mf = 0; mf < 2; mf++) {
                    mma16816(S[mf][0], qf[mf][kc], kb);
                    mma16816(S[mf][1], qf[mf][kc], kb + 2);
                }
            }
            uint32_t pa[2][4];
#pragma unroll
            for (int mf = 0; mf < 2; mf++) {
                pa[mf][0] = h2ex2(pack2h(S[mf][0][0], S[mf][0][1]));
                pa[mf][1] = h2ex2(pack2h(S[mf][0][2], S[mf][0][3]));
                pa[mf][2] = h2ex2(pack2h(S[mf][1][0], S[mf][1][1]));
                pa[mf][3] = h2ex2(pack2h(S[mf][1][2], S[mf][1][3]));
                float2 f0 = h22f2(pa[mf][0]), f1 = h22f2(pa[mf][1]);
                float2 f2 = h22f2(pa[mf][2]), f3 = h22f2(pa[mf][3]);
                lsum[mf][0] += f0.x + f0.y + f2.x + f2.y;
                lsum[mf][1] += f1.x + f1.y + f3.x + f3.y;
            }
#pragma unroll
            for (int vg = 0; vg < 4; vg++) {
                uint32_t vb[4];
                ldsm4(vb, tb + KT + (uint32_t)((vg * 16 + prow) * RBV + pc * 32 + pcol));
#pragma unroll
                for (int mf = 0; mf < 2; mf++) {
                    mma16816(O[mf][2 * vg],     pa[mf], vb);
                    mma16816(O[mf][2 * vg + 1], pa[mf], vb + 2);
                }
            }
        }
    }

    // Row sums over each quad, normalize, store X
#pragma unroll
    for (int mf = 0; mf < 2; mf++)
#pragma unroll
        for (int hf = 0; hf < 2; hf++) {
            lsum[mf][hf] += __shfl_xor_sync(0xffffffffu, lsum[mf][hf], 1, 4);
            lsum[mf][hf] += __shfl_xor_sync(0xffffffffu, lsum[mf][hf], 2, 4);
        }

    const int b = bh >> 4, h = bh & 15;
#pragma unroll
    for (int mf = 0; mf < 2; mf++) {
        const float inv0 = 1.0f / lsum[mf][0], inv1 = 1.0f / lsum[mf][1];
        const int m0 = mblk + w * 32 + mf * 16 + (lane >> 2);
#pragma unroll
        for (int gd = 0; gd < 8; gd++) {
            int cc = h * 64 + gd * 8 + 2 * (lane & 3);
            size_t o = (size_t)(b * 2048 + m0) * 1024 + cc;
            *(uint32_t*)(g_X + o) = pack2h(O[mf][gd][0] * inv0, O[mf][gd][1] * inv0);
            o = (size_t)(b * 2048 + m0 + 8) * 1024 + cc;
            *(uint32_t*)(g_X + o) = pack2h(O[mf][gd][2] * inv1, O[mf][gd][3] * inv1);
        }
    }
}

// ---------------------------------------------------------------------------
extern "C" void kernel_launch(void* const* d_in, const int* in_sizes, int n_in,
                              void* d_out, int out_size)
{
    const float* ref   = (const float*)d_in[0];
    const float* tgt   = (const float*)d_in[1];
    const float* Wq    = (const float*)d_in[2];
    const float* Wkv   = (const float*)d_in[3];
    const float* Wproj = (const float*)d_in[4];
    const float* bproj = (const float*)d_in[5];
    float* out = (float*)d_out;

    cudaFuncSetAttribute(gemm01,   cudaFuncAttributeMaxDynamicSharedMemorySize, GEMM_SMEM);
    cudaFuncSetAttribute(gemm2,    cudaFuncAttributeMaxDynamicSharedMemorySize, GEMM_SMEM);
    cudaFuncSetAttribute(attn_mma, cudaFuncAttributeMaxDynamicSharedMemorySize, ATTN_SMEM);

    prep_all<<<12288, 256>>>(tgt, ref, Wq, Wkv, Wproj);    // flat-packed, zero waste

    gemm01<<<dim3(24, 32), 128, GEMM_SMEM>>>();            // Q-proj + KV-proj merged
    attn_mma<<<dim3(16, 32), 128, ATTN_SMEM>>>();          // attention
    gemm2<<<dim3(8, 32), 128, GEMM_SMEM>>>(bproj, out);    // out-proj
}